// round 1
// baseline (speedup 1.0000x reference)
#include <cuda_runtime.h>
#include <cstdint>

// ---------------------------------------------------------------------------
// InteractionBlock (SchNet cfconv) — B=8, A=1024, N=64, F=128, S=50
// tf32 mma.sync GEMMs + fp32 gather/reduce epilogues.
// ---------------------------------------------------------------------------

#define BA     8192          // B*A rows
#define FDIM   128
#define NNBR   64
#define SDIM   50
#define LN2F   0.6931471805599453f

// scratch (no cudaMalloc allowed)
__device__ float g_y[BA * FDIM];
__device__ float g_z[BA * FDIM];
__device__ float g_h[BA * FDIM];

__device__ __forceinline__ float sspf(float x) {
    // softplus(x) - ln2, numerically stable
    return fmaxf(x, 0.f) + __logf(1.f + __expf(-fabsf(x))) - LN2F;
}

__device__ __forceinline__ float to_tf32(float x) {
    uint32_t u;
    asm("cvt.rna.tf32.f32 %0, %1;" : "=r"(u) : "f"(x));
    return __uint_as_float(u);
}

__device__ __forceinline__ void mma_tf32(float* d,
                                         uint32_t a0, uint32_t a1, uint32_t a2, uint32_t a3,
                                         uint32_t b0, uint32_t b1) {
    asm volatile(
        "mma.sync.aligned.m16n8k8.row.col.f32.tf32.tf32.f32 "
        "{%0,%1,%2,%3}, {%4,%5,%6,%7}, {%8,%9}, {%0,%1,%2,%3};\n"
        : "+f"(d[0]), "+f"(d[1]), "+f"(d[2]), "+f"(d[3])
        : "r"(a0), "r"(a1), "r"(a2), "r"(a3), "r"(b0), "r"(b1));
}

// ---------------------------------------------------------------------------
// Generic 128-wide dense layer:  out = [post ops]( ssp(in) @ W + bias )
// M-tile = 64 rows/CTA, 4 warps (one 16-row m-tile each), K = N = 128.
// ---------------------------------------------------------------------------
#define GPAD 132   // smem row stride (floats): stride%32==4 -> A frags conflict-free

template<int POST_SSP, int ADD_RES, int ADD_MASKX>
__global__ void __launch_bounds__(128)
dense128(const float* __restrict__ in, const float* __restrict__ W,
         const float* __restrict__ bias, const float* __restrict__ res,
         const float* __restrict__ xin, const float* __restrict__ mpar,
         float* __restrict__ out)
{
    extern __shared__ float sm[];
    float* A_s = sm;                 // [64][GPAD]
    float* W_s = sm + 64 * GPAD;     // [128][GPAD]

    const int tid  = threadIdx.x;
    const int warp = tid >> 5, lane = tid & 31;
    const int g = lane >> 2, c = lane & 3;
    const int row0 = blockIdx.x * 64;

    // load W (round to tf32 once)
    for (int i = tid; i < 128 * 32; i += 128) {
        int r = i >> 5, c4 = (i & 31) << 2;
        float4 v = *reinterpret_cast<const float4*>(W + r * 128 + c4);
        v.x = to_tf32(v.x); v.y = to_tf32(v.y); v.z = to_tf32(v.z); v.w = to_tf32(v.w);
        *reinterpret_cast<float4*>(W_s + r * GPAD + c4) = v;
    }
    // load A = tf32(ssp(in))
    for (int i = tid; i < 64 * 32; i += 128) {
        int r = i >> 5, c4 = (i & 31) << 2;
        float4 v = *reinterpret_cast<const float4*>(in + (size_t)(row0 + r) * 128 + c4);
        v.x = to_tf32(sspf(v.x)); v.y = to_tf32(sspf(v.y));
        v.z = to_tf32(sspf(v.z)); v.w = to_tf32(sspf(v.w));
        *reinterpret_cast<float4*>(A_s + r * GPAD + c4) = v;
    }
    __syncthreads();

    float acc[16][4];
    #pragma unroll
    for (int nt = 0; nt < 16; nt++) { acc[nt][0] = acc[nt][1] = acc[nt][2] = acc[nt][3] = 0.f; }

    const int ar0 = (warp * 16 + g) * GPAD;
    const int ar1 = (warp * 16 + g + 8) * GPAD;
    #pragma unroll
    for (int k = 0; k < 16; k++) {
        int kc = k * 8 + c;
        uint32_t a0 = __float_as_uint(A_s[ar0 + kc]);
        uint32_t a1 = __float_as_uint(A_s[ar1 + kc]);
        uint32_t a2 = __float_as_uint(A_s[ar0 + kc + 4]);
        uint32_t a3 = __float_as_uint(A_s[ar1 + kc + 4]);
        #pragma unroll
        for (int nt = 0; nt < 16; nt++) {
            uint32_t b0 = __float_as_uint(W_s[kc * GPAD + nt * 8 + g]);
            uint32_t b1 = __float_as_uint(W_s[(kc + 4) * GPAD + nt * 8 + g]);
            mma_tf32(acc[nt], a0, a1, a2, a3, b0, b1);
        }
    }

    // epilogue
    const int r0 = row0 + warp * 16 + g;
    const int r1 = r0 + 8;
    #pragma unroll
    for (int nt = 0; nt < 16; nt++) {
        #pragma unroll
        for (int e = 0; e < 2; e++) {
            int f = nt * 8 + c * 2 + e;
            float b  = bias[f];
            float v0 = acc[nt][e]     + b;
            float v1 = acc[nt][2 + e] + b;
            if (POST_SSP) { v0 = sspf(v0); v1 = sspf(v1); }
            if (ADD_RES)  { v0 += res[(size_t)r0 * 128 + f]; v1 += res[(size_t)r1 * 128 + f]; }
            if (ADD_MASKX) {
                float m = mpar[f];
                v0 += m * xin[(size_t)r0 * 128 + f];
                v1 += m * xin[(size_t)r1 * 128 + f];
            }
            out[(size_t)r0 * 128 + f] = v0;
            out[(size_t)r1 * 128 + f] = v1;
        }
    }
}

// ---------------------------------------------------------------------------
// cfconv: per atom p=(b,a):
//   Wf[n,f] = sum_s f_ij[p,n,s] * G[s,f]            (tf32 MMA, K padded 50->56)
//   y2[f]   = sum_n Wf[n,f] * mask[p,n] * y[b,nbr[p,n],f]   (fp32)
//   out[p,f] = y[p,f] + y2[f]
// 512 CTAs x 16 atoms; G cached in smem per CTA.
// ---------------------------------------------------------------------------
#define APAD 60    // f_ij smem row stride (stride%32==28 -> conflict-free A frags)

__global__ void __launch_bounds__(128)
conv_kernel(const float* __restrict__ y, const int* __restrict__ nbrs,
            const float* __restrict__ mask, const float* __restrict__ fij,
            const float* __restrict__ GW, float* __restrict__ out)
{
    extern __shared__ float sm[];
    float* A_s = sm;                         // [64][APAD]
    float* G_s = A_s + 64 * APAD;            // [56][GPAD]
    float* Ym  = G_s + 56 * GPAD;            // [64][GPAD]
    float* red = Ym  + 64 * GPAD;            // [32][GPAD]
    __shared__ int   nb_s[64];
    __shared__ float mk_s[64];

    const int tid  = threadIdx.x;
    const int warp = tid >> 5, lane = tid & 31;
    const int g = lane >> 2, c = lane & 3;

    // zero K-pad region of A and all of G (pad rows must be 0)
    for (int i = tid; i < 64 * APAD; i += 128) A_s[i] = 0.f;
    for (int i = tid; i < 56 * GPAD; i += 128) G_s[i] = 0.f;
    __syncthreads();
    for (int i = tid; i < SDIM * 128; i += 128) {
        int s = i >> 7, f = i & 127;
        G_s[s * GPAD + f] = to_tf32(GW[i]);
    }

    const int p0 = blockIdx.x * 16;
    for (int it = 0; it < 16; it++) {
        const int p = p0 + it;
        const int b = p >> 10;

        __syncthreads();   // G ready (first iter); red/Ym free (later iters)

        if (tid < 64) {
            nb_s[tid] = nbrs[(size_t)p * NNBR + tid];
            mk_s[tid] = mask[(size_t)p * NNBR + tid];
        }
        const float* fp = fij + (size_t)p * (NNBR * SDIM);
        for (int i = tid; i < NNBR * SDIM; i += 128) {
            int n = i / SDIM, s = i - n * SDIM;
            A_s[n * APAD + s] = to_tf32(fp[i]);
        }
        __syncthreads();

        // gather + mask neighbor rows of y (fp32, mostly L2 hits: y is 4MB)
        const float* yb = y + (((size_t)b) << 10) * 128;
        #pragma unroll
        for (int j = 0; j < 16; j++) {
            int idx = tid + j * 128;
            int r = idx >> 5, col = (idx & 31) << 2;
            int nb = nb_s[r];
            float m = mk_s[r];
            float4 v = *reinterpret_cast<const float4*>(yb + (size_t)nb * 128 + col);
            v.x *= m; v.y *= m; v.z *= m; v.w *= m;
            *reinterpret_cast<float4*>(Ym + r * GPAD + col) = v;
        }
        __syncthreads();

        // Wf = F @ G : M=64 (one 16-row m-tile per warp), N=128, K=56
        float acc[16][4];
        #pragma unroll
        for (int nt = 0; nt < 16; nt++) { acc[nt][0] = acc[nt][1] = acc[nt][2] = acc[nt][3] = 0.f; }

        const int ar0 = (warp * 16 + g) * APAD;
        const int ar1 = (warp * 16 + g + 8) * APAD;
        #pragma unroll
        for (int k = 0; k < 7; k++) {
            int kc = k * 8 + c;
            uint32_t a0 = __float_as_uint(A_s[ar0 + kc]);
            uint32_t a1 = __float_as_uint(A_s[ar1 + kc]);
            uint32_t a2 = __float_as_uint(A_s[ar0 + kc + 4]);
            uint32_t a3 = __float_as_uint(A_s[ar1 + kc + 4]);
            #pragma unroll
            for (int nt = 0; nt < 16; nt++) {
                uint32_t b0 = __float_as_uint(G_s[kc * GPAD + nt * 8 + g]);
                uint32_t b1 = __float_as_uint(G_s[(kc + 4) * GPAD + nt * 8 + g]);
                mma_tf32(acc[nt], a0, a1, a2, a3, b0, b1);
            }
        }

        // pass1: v = Wf[n,f]*Ym[n,f] reduced over this thread's 2 n-rows
        const int n0 = (warp * 16 + g) * GPAD;
        const int n1 = n0 + 8 * GPAD;
        const int rrow = (warp * 8 + g) * GPAD;
        #pragma unroll
        for (int nt = 0; nt < 16; nt++) {
            #pragma unroll
            for (int e = 0; e < 2; e++) {
                int f = nt * 8 + c * 2 + e;
                red[rrow + f] = acc[nt][e] * Ym[n0 + f] + acc[nt][2 + e] * Ym[n1 + f];
            }
        }
        __syncthreads();

        // pass2: reduce 32 groups -> y2[f]; out = y + y2
        {
            float s = 0.f;
            #pragma unroll
            for (int j = 0; j < 32; j++) s += red[j * GPAD + tid];
            out[(size_t)p * 128 + tid] = y[(size_t)p * 128 + tid] + s;
        }
    }
}

// ---------------------------------------------------------------------------
// launch
// ---------------------------------------------------------------------------
extern "C" void kernel_launch(void* const* d_in, const int* in_sizes, int n_in,
                              void* d_out, int out_size)
{
    const float* x       = (const float*)d_in[0];
    // d_in[1] = r_ij (unused by reference)
    const int*   nbrs    = (const int*)  d_in[2];
    const float* nmask   = (const float*)d_in[3];
    const float* fij     = (const float*)d_in[4];
    const float* in2f_W  = (const float*)d_in[5];
    const float* in2f_b  = (const float*)d_in[6];
    const float* G_W     = (const float*)d_in[7];
    const float* res_Ws  = (const float*)d_in[8];
    const float* res_bs  = (const float*)d_in[9];
    const float* dense_W = (const float*)d_in[10];
    const float* dense_b = (const float*)d_in[11];
    const float* mask_p  = (const float*)d_in[12];
    float* out = (float*)d_out;

    float *y, *z, *h;
    cudaGetSymbolAddress((void**)&y, g_y);
    cudaGetSymbolAddress((void**)&z, g_z);
    cudaGetSymbolAddress((void**)&h, g_h);

    const int smem_gemm = (64 * GPAD + 128 * GPAD) * sizeof(float);                 // ~99 KB
    const int smem_conv = (64 * APAD + 56 * GPAD + 64 * GPAD + 32 * GPAD) * sizeof(float); // ~94 KB

    cudaFuncSetAttribute(dense128<1,0,0>, cudaFuncAttributeMaxDynamicSharedMemorySize, smem_gemm);
    cudaFuncSetAttribute(dense128<0,0,0>, cudaFuncAttributeMaxDynamicSharedMemorySize, smem_gemm);
    cudaFuncSetAttribute(dense128<0,1,0>, cudaFuncAttributeMaxDynamicSharedMemorySize, smem_gemm);
    cudaFuncSetAttribute(dense128<0,0,1>, cudaFuncAttributeMaxDynamicSharedMemorySize, smem_gemm);
    cudaFuncSetAttribute(conv_kernel,     cudaFuncAttributeMaxDynamicSharedMemorySize, smem_conv);

    const int GEMM_GRID = BA / 64;   // 128 CTAs

    // y = ssp( ssp(x) @ in2f_W + b )
    dense128<1,0,0><<<GEMM_GRID, 128, smem_gemm>>>(x, in2f_W, in2f_b,
                                                   nullptr, nullptr, nullptr, y);
    // z = y + cfconv(y)
    conv_kernel<<<BA / 16, 128, smem_conv>>>(y, nbrs, nmask, fij, G_W, z);
    // residual MLP: h1 = ssp(z)@W0+b0 ; h2 = ssp(h1)@W1+b1 ; z = z + ssp(h2)@W2+b2
    dense128<0,0,0><<<GEMM_GRID, 128, smem_gemm>>>(z, res_Ws,             res_bs,
                                                   nullptr, nullptr, nullptr, h);
    dense128<0,0,0><<<GEMM_GRID, 128, smem_gemm>>>(h, res_Ws + 128*128,   res_bs + 128,
                                                   nullptr, nullptr, nullptr, h);
    dense128<0,1,0><<<GEMM_GRID, 128, smem_gemm>>>(h, res_Ws + 2*128*128, res_bs + 256,
                                                   z, nullptr, nullptr, z);
    // out = ssp(z) @ dense_W + dense_b + mask_p * x
    dense128<0,0,1><<<GEMM_GRID, 128, smem_gemm>>>(z, dense_W, dense_b,
                                                   nullptr, x, mask_p, out);
}

// round 3
// speedup vs baseline: 2.7450x; 2.7450x over previous
#include <cuda_runtime.h>
#include <cstdint>

// ---------------------------------------------------------------------------
// InteractionBlock — B=8, A=1024, N=64, F=128, S=50
// 3 kernels: in2f dense | pipelined cfconv | fused 4-stage MLP
// tf32 mma.sync, fp32 accumulate, cp.async pipelines.
// ---------------------------------------------------------------------------

#define BA   8192
#define LN2F 0.6931471805599453f
#define GPAD 132          // B/W smem row stride
#define APAD 60           // f_ij smem row stride

__device__ float g_y[BA * 128];
__device__ float g_z[BA * 128];

__device__ __forceinline__ float sspf(float x) {
    return fmaxf(x, 0.f) + __logf(1.f + __expf(-fabsf(x))) - LN2F;
}
__device__ __forceinline__ float to_tf32(float x) {
    uint32_t u; asm("cvt.rna.tf32.f32 %0, %1;" : "=r"(u) : "f"(x));
    return __uint_as_float(u);
}
__device__ __forceinline__ void mma_tf32(float* d,
        uint32_t a0, uint32_t a1, uint32_t a2, uint32_t a3,
        uint32_t b0, uint32_t b1) {
    asm volatile(
        "mma.sync.aligned.m16n8k8.row.col.f32.tf32.tf32.f32 "
        "{%0,%1,%2,%3},{%4,%5,%6,%7},{%8,%9},{%0,%1,%2,%3};\n"
        : "+f"(d[0]), "+f"(d[1]), "+f"(d[2]), "+f"(d[3])
        : "r"(a0), "r"(a1), "r"(a2), "r"(a3), "r"(b0), "r"(b1));
}

__device__ __forceinline__ uint32_t smem_u32(const void* p) {
    return (uint32_t)__cvta_generic_to_shared(p);
}
__device__ __forceinline__ void cp16(void* dst, const void* src) {
    asm volatile("cp.async.cg.shared.global [%0], [%1], 16;\n"
                 :: "r"(smem_u32(dst)), "l"(src));
}
__device__ __forceinline__ void cp8(void* dst, const void* src) {
    asm volatile("cp.async.ca.shared.global [%0], [%1], 8;\n"
                 :: "r"(smem_u32(dst)), "l"(src));
}
#define CP_COMMIT() asm volatile("cp.async.commit_group;\n")
#define CP_WAIT(n)  asm volatile("cp.async.wait_group %0;\n" :: "n"(n))

// warp computes MT*16 rows x 32 cols (cols w*32..w*32+31); B regs reused over m
template<int MT, int KS, int SA>
__device__ __forceinline__ void warp_mma(const float* __restrict__ A_s,
                                         const float* __restrict__ B_s,
                                         int w, int g, int c,
                                         float acc[MT][4][4])
{
    #pragma unroll
    for (int k = 0; k < KS; k++) {
        const int kc = k * 8 + c;
        uint32_t b0[4], b1[4];
        #pragma unroll
        for (int nt = 0; nt < 4; nt++) {
            const int col = w * 32 + nt * 8 + g;
            b0[nt] = __float_as_uint(B_s[kc * GPAD + col]);
            b1[nt] = __float_as_uint(B_s[(kc + 4) * GPAD + col]);
        }
        #pragma unroll
        for (int m = 0; m < MT; m++) {
            const int r0 = (m * 16 + g) * SA + kc;
            const int r1 = (m * 16 + g + 8) * SA + kc;
            uint32_t a0 = __float_as_uint(A_s[r0]);
            uint32_t a1 = __float_as_uint(A_s[r1]);
            uint32_t a2 = __float_as_uint(A_s[r0 + 4]);
            uint32_t a3 = __float_as_uint(A_s[r1 + 4]);
            #pragma unroll
            for (int nt = 0; nt < 4; nt++)
                mma_tf32(acc[m][nt], a0, a1, a2, a3, b0[nt], b1[nt]);
        }
    }
}

// ---------------------------------------------------------------------------
// in2f: y = ssp( ssp(x) @ W + b ).  32 rows/CTA, grid 256.
// ---------------------------------------------------------------------------
__global__ void __launch_bounds__(128)
in2f_kernel(const float* __restrict__ x, const float* __restrict__ W,
            const float* __restrict__ bias, float* __restrict__ y)
{
    extern __shared__ float sm[];
    float* A_s = sm;             // 32 x GPAD
    float* W_s = sm + 32 * GPAD; // 128 x GPAD
    const int tid = threadIdx.x, w = tid >> 5, lane = tid & 31;
    const int g = lane >> 2, c = lane & 3;
    const int row0 = blockIdx.x * 32;

    for (int i = tid; i < 4096; i += 128) {
        int r = i >> 5, c4 = (i & 31) << 2;
        cp16(W_s + r * GPAD + c4, W + r * 128 + c4);
    }
    CP_COMMIT();
    for (int i = tid; i < 1024; i += 128) {
        int r = i >> 5, c4 = (i & 31) << 2;
        float4 v = *reinterpret_cast<const float4*>(x + (size_t)(row0 + r) * 128 + c4);
        v.x = to_tf32(sspf(v.x)); v.y = to_tf32(sspf(v.y));
        v.z = to_tf32(sspf(v.z)); v.w = to_tf32(sspf(v.w));
        *reinterpret_cast<float4*>(A_s + r * GPAD + c4) = v;
    }
    CP_WAIT(0);
    __syncthreads();

    float acc[2][4][4];
    #pragma unroll
    for (int m = 0; m < 2; m++)
        #pragma unroll
        for (int nt = 0; nt < 4; nt++)
            acc[m][nt][0] = acc[m][nt][1] = acc[m][nt][2] = acc[m][nt][3] = 0.f;
    warp_mma<2, 16, GPAD>(A_s, W_s, w, g, c, acc);

    #pragma unroll
    for (int m = 0; m < 2; m++) {
        const int r0 = row0 + m * 16 + g, r1 = r0 + 8;
        #pragma unroll
        for (int nt = 0; nt < 4; nt++)
            #pragma unroll
            for (int e = 0; e < 2; e++) {
                int f = w * 32 + nt * 8 + c * 2 + e;
                float b = bias[f];
                y[(size_t)r0 * 128 + f] = sspf(acc[m][nt][e] + b);
                y[(size_t)r1 * 128 + f] = sspf(acc[m][nt][2 + e] + b);
            }
    }
}

// ---------------------------------------------------------------------------
// fused MLP: h1=ssp(z)@W0+b0; h2=ssp(h1)@W1+b1; h3=ssp(h2)@W2+b2;
//            out = ssp(z+h3)@dW + db + mask_p*x.   32 rows/CTA, grid 256.
// ---------------------------------------------------------------------------
__global__ void __launch_bounds__(128)
mlp_kernel(const float* __restrict__ z, const float* __restrict__ resW,
           const float* __restrict__ resB, const float* __restrict__ dW,
           const float* __restrict__ dB, const float* __restrict__ mpar,
           const float* __restrict__ x, float* __restrict__ out)
{
    extern __shared__ float sm[];
    float* A_s = sm;
    float* W_s = sm + 32 * GPAD;
    const int tid = threadIdx.x, w = tid >> 5, lane = tid & 31;
    const int g = lane >> 2, c = lane & 3;
    const int row0 = blockIdx.x * 32;

    const float* Wp[4] = { resW, resW + 16384, resW + 32768, dW };

    // stage 0
    for (int i = tid; i < 4096; i += 128) {
        int r = i >> 5, c4 = (i & 31) << 2;
        cp16(W_s + r * GPAD + c4, Wp[0] + r * 128 + c4);
    }
    CP_COMMIT();
    for (int i = tid; i < 1024; i += 128) {
        int r = i >> 5, c4 = (i & 31) << 2;
        float4 v = *reinterpret_cast<const float4*>(z + (size_t)(row0 + r) * 128 + c4);
        v.x = to_tf32(sspf(v.x)); v.y = to_tf32(sspf(v.y));
        v.z = to_tf32(sspf(v.z)); v.w = to_tf32(sspf(v.w));
        *reinterpret_cast<float4*>(A_s + r * GPAD + c4) = v;
    }
    CP_WAIT(0);
    __syncthreads();

    float acc[2][4][4];
    #pragma unroll
    for (int m = 0; m < 2; m++)
        #pragma unroll
        for (int nt = 0; nt < 4; nt++)
            acc[m][nt][0] = acc[m][nt][1] = acc[m][nt][2] = acc[m][nt][3] = 0.f;
    warp_mma<2, 16, GPAD>(A_s, W_s, w, g, c, acc);

    #pragma unroll
    for (int s = 1; s < 4; s++) {
        __syncthreads();   // all warps done reading A_s / W_s
        for (int i = tid; i < 4096; i += 128) {
            int r = i >> 5, c4 = (i & 31) << 2;
            cp16(W_s + r * GPAD + c4, Wp[s] + r * 128 + c4);
        }
        CP_COMMIT();
        const float* bs = resB + (s - 1) * 128;
        #pragma unroll
        for (int m = 0; m < 2; m++) {
            const int gr0 = row0 + m * 16 + g, gr1 = gr0 + 8;
            const int sr0 = (m * 16 + g) * GPAD, sr1 = sr0 + 8 * GPAD;
            #pragma unroll
            for (int nt = 0; nt < 4; nt++)
                #pragma unroll
                for (int e = 0; e < 2; e++) {
                    int f = w * 32 + nt * 8 + c * 2 + e;
                    float b = bs[f];
                    float v0 = acc[m][nt][e] + b;
                    float v1 = acc[m][nt][2 + e] + b;
                    if (s == 3) {
                        v0 += z[(size_t)gr0 * 128 + f];
                        v1 += z[(size_t)gr1 * 128 + f];
                    }
                    A_s[sr0 + f] = to_tf32(sspf(v0));
                    A_s[sr1 + f] = to_tf32(sspf(v1));
                }
        }
        #pragma unroll
        for (int m = 0; m < 2; m++)
            #pragma unroll
            for (int nt = 0; nt < 4; nt++)
                acc[m][nt][0] = acc[m][nt][1] = acc[m][nt][2] = acc[m][nt][3] = 0.f;
        CP_WAIT(0);
        __syncthreads();
        warp_mma<2, 16, GPAD>(A_s, W_s, w, g, c, acc);
    }

    // epilogue: out = acc + dB + mask_p * x
    #pragma unroll
    for (int m = 0; m < 2; m++) {
        const int r0 = row0 + m * 16 + g, r1 = r0 + 8;
        #pragma unroll
        for (int nt = 0; nt < 4; nt++)
            #pragma unroll
            for (int e = 0; e < 2; e++) {
                int f = w * 32 + nt * 8 + c * 2 + e;
                float b = dB[f], mp = mpar[f];
                out[(size_t)r0 * 128 + f] = acc[m][nt][e]     + b + mp * x[(size_t)r0 * 128 + f];
                out[(size_t)r1 * 128 + f] = acc[m][nt][2 + e] + b + mp * x[(size_t)r1 * 128 + f];
            }
    }
}

// ---------------------------------------------------------------------------
// cfconv, pipelined.  16 atoms/CTA, grid 512, 128 threads.
//   Wf = f_ij @ G (tf32 MMA, K 50->56), y2 = sum_n mask*Wf*y[nbr], z = y + y2
// ---------------------------------------------------------------------------
__global__ void __launch_bounds__(128)
conv_kernel(const float* __restrict__ y, const int* __restrict__ nbrs,
            const float* __restrict__ mask, const float* __restrict__ fij,
            const float* __restrict__ GW, float* __restrict__ out)
{
    extern __shared__ float sm[];
    float* G_s = sm;                       // 56 x GPAD
    float* A_s = G_s + 56 * GPAD;          // 2 x 64 x APAD
    float* Ym  = A_s + 2 * 64 * APAD;      // 64 x GPAD
    __shared__ int   nb_s[2][64];
    __shared__ float mk_s[2][64];

    const int tid = threadIdx.x, w = tid >> 5, lane = tid & 31;
    const int g = lane >> 2, c = lane & 3;

    // zero A bufs (pad cols must be 0) and G (pad rows must be 0)
    for (int i = tid; i < 2 * 64 * APAD; i += 128) A_s[i] = 0.f;
    for (int i = tid; i < 56 * GPAD;     i += 128) G_s[i] = 0.f;
    __syncthreads();
    for (int i = tid; i < 1600; i += 128) {     // 50 rows x 32 float4
        int r = i >> 5, c4 = (i & 31) << 2;
        float4 v = *reinterpret_cast<const float4*>(GW + r * 128 + c4);
        v.x = to_tf32(v.x); v.y = to_tf32(v.y); v.z = to_tf32(v.z); v.w = to_tf32(v.w);
        *reinterpret_cast<float4*>(G_s + r * GPAD + c4) = v;
    }

    const int p0 = blockIdx.x * 16;

    // prefetch atom 0 -> buf 0
    {
        const float* fp = fij + (size_t)p0 * 3200;
        for (int i = tid; i < 1600; i += 128) {
            int n = i / 25, s2 = i - n * 25;
            cp8(A_s + n * APAD + s2 * 2, fp + i * 2);
        }
        if (tid < 16) {
            cp16(&nb_s[0][tid * 4], nbrs + (size_t)p0 * 64 + tid * 4);
            cp16(&mk_s[0][tid * 4], mask + (size_t)p0 * 64 + tid * 4);
        }
    }
    CP_COMMIT();

    for (int it = 0; it < 16; it++) {
        const int cur = it & 1, nxt = cur ^ 1;
        const int p = p0 + it;
        const int b = p >> 10;

        CP_WAIT(0);
        __syncthreads();  // A_s[cur]/nb/mk ready; Ym & A_s[nxt] free for reuse

        // async gather of neighbor rows into Ym: 64 rows x 32 float4 = 2048
        const float* yb = y + (((size_t)b) << 10) * 128;
        #pragma unroll
        for (int j = 0; j < 16; j++) {
            int idx = tid + j * 128;
            int row = idx >> 5, col = (idx & 31) << 2;
            cp16(Ym + row * GPAD + col,
                 yb + (size_t)nb_s[cur][row] * 128 + col);
        }
        CP_COMMIT();   // group: gather

        // prefetch next atom while this one's MMA runs
        if (it < 15) {
            const float* fp = fij + (size_t)(p + 1) * 3200;
            for (int i = tid; i < 1600; i += 128) {
                int n = i / 25, s2 = i - n * 25;
                cp8(A_s + nxt * 64 * APAD + n * APAD + s2 * 2, fp + i * 2);
            }
            if (tid < 16) {
                cp16(&nb_s[nxt][tid * 4], nbrs + (size_t)(p + 1) * 64 + tid * 4);
                cp16(&mk_s[nxt][tid * 4], mask + (size_t)(p + 1) * 64 + tid * 4);
            }
        }
        CP_COMMIT();   // group: prefetch (may be empty on last iter)

        // Wf = F @ G : warp tile m64 x n32
        float acc[4][4][4];
        #pragma unroll
        for (int m = 0; m < 4; m++)
            #pragma unroll
            for (int nt = 0; nt < 4; nt++)
                acc[m][nt][0] = acc[m][nt][1] = acc[m][nt][2] = acc[m][nt][3] = 0.f;
        warp_mma<4, 7, APAD>(A_s + cur * 64 * APAD, G_s, w, g, c, acc);

        float mk0[4], mk1[4];
        #pragma unroll
        for (int m = 0; m < 4; m++) {
            mk0[m] = mk_s[cur][m * 16 + g];
            mk1[m] = mk_s[cur][m * 16 + g + 8];
        }

        CP_WAIT(1);        // gather complete (prefetch may still be in flight)
        __syncthreads();   // Ym visible to all warps

        // y2[f] = sum_n mask[n]*Wf[n,f]*y[nbr[n],f];  n-reduce: 8 rows in-thread,
        // then butterfly over the 8 g-lane groups (lane bits 2..4).
        #pragma unroll
        for (int nt = 0; nt < 4; nt++)
            #pragma unroll
            for (int e = 0; e < 2; e++) {
                const int f = w * 32 + nt * 8 + c * 2 + e;
                float s = 0.f;
                #pragma unroll
                for (int m = 0; m < 4; m++) {
                    s += acc[m][nt][e]     * mk0[m] * Ym[(m * 16 + g)     * GPAD + f];
                    s += acc[m][nt][2 + e] * mk1[m] * Ym[(m * 16 + g + 8) * GPAD + f];
                }
                s += __shfl_xor_sync(0xffffffffu, s, 16);
                s += __shfl_xor_sync(0xffffffffu, s, 8);
                s += __shfl_xor_sync(0xffffffffu, s, 4);
                if (g == 0)
                    out[(size_t)p * 128 + f] = y[(size_t)p * 128 + f] + s;
            }
    }
}

// ---------------------------------------------------------------------------
extern "C" void kernel_launch(void* const* d_in, const int* in_sizes, int n_in,
                              void* d_out, int out_size)
{
    const float* x       = (const float*)d_in[0];
    const int*   nbrs    = (const int*)  d_in[2];
    const float* nmask   = (const float*)d_in[3];
    const float* fij     = (const float*)d_in[4];
    const float* in2f_W  = (const float*)d_in[5];
    const float* in2f_b  = (const float*)d_in[6];
    const float* G_W     = (const float*)d_in[7];
    const float* res_Ws  = (const float*)d_in[8];
    const float* res_bs  = (const float*)d_in[9];
    const float* dense_W = (const float*)d_in[10];
    const float* dense_b = (const float*)d_in[11];
    const float* mask_p  = (const float*)d_in[12];
    float* out = (float*)d_out;

    float *y, *z;
    cudaGetSymbolAddress((void**)&y, g_y);
    cudaGetSymbolAddress((void**)&z, g_z);

    const int smem_d    = (32 * GPAD + 128 * GPAD) * sizeof(float);          // ~84 KB
    const int smem_conv = (56 * GPAD + 2 * 64 * APAD + 64 * GPAD) * sizeof(float); // ~94 KB

    cudaFuncSetAttribute(in2f_kernel, cudaFuncAttributeMaxDynamicSharedMemorySize, smem_d);
    cudaFuncSetAttribute(mlp_kernel,  cudaFuncAttributeMaxDynamicSharedMemorySize, smem_d);
    cudaFuncSetAttribute(conv_kernel, cudaFuncAttributeMaxDynamicSharedMemorySize, smem_conv);

    in2f_kernel<<<BA / 32, 128, smem_d>>>(x, in2f_W, in2f_b, y);
    conv_kernel<<<BA / 16, 128, smem_conv>>>(y, nbrs, nmask, fij, G_W, z);
    mlp_kernel<<<BA / 32, 128, smem_d>>>(z, res_Ws, res_bs, dense_W, dense_b,
                                         mask_p, x, out);
}

// round 4
// speedup vs baseline: 2.9850x; 1.0874x over previous
#include <cuda_runtime.h>
#include <cuda_fp16.h>
#include <cstdint>

// ---------------------------------------------------------------------------
// InteractionBlock — B=8, A=1024, N=64, F=128, S=50
// in2f dense (tf32) | cfconv (fp16 MMA, deep pipeline) | fused 4-stage MLP (tf32)
// ---------------------------------------------------------------------------

#define BA   8192
#define LN2F 0.6931471805599453f
#define GPAD 132     // fp32 smem row stride
#define KHP  72      // half smem row stride (conv A/G): bank = 4g+c, conflict-free

__device__ float g_y[BA * 128];
__device__ float g_z[BA * 128];

__device__ __forceinline__ float sspf(float x) {
    return fmaxf(x, 0.f) + __logf(1.f + __expf(-fabsf(x))) - LN2F;
}
__device__ __forceinline__ float to_tf32(float x) {
    uint32_t u; asm("cvt.rna.tf32.f32 %0, %1;" : "=r"(u) : "f"(x));
    return __uint_as_float(u);
}
__device__ __forceinline__ void mma_tf32(float* d,
        uint32_t a0, uint32_t a1, uint32_t a2, uint32_t a3,
        uint32_t b0, uint32_t b1) {
    asm volatile(
        "mma.sync.aligned.m16n8k8.row.col.f32.tf32.tf32.f32 "
        "{%0,%1,%2,%3},{%4,%5,%6,%7},{%8,%9},{%0,%1,%2,%3};\n"
        : "+f"(d[0]), "+f"(d[1]), "+f"(d[2]), "+f"(d[3])
        : "r"(a0), "r"(a1), "r"(a2), "r"(a3), "r"(b0), "r"(b1));
}
__device__ __forceinline__ void mma_f16(float* d,
        uint32_t a0, uint32_t a1, uint32_t a2, uint32_t a3,
        uint32_t b0, uint32_t b1) {
    asm volatile(
        "mma.sync.aligned.m16n8k16.row.col.f32.f16.f16.f32 "
        "{%0,%1,%2,%3},{%4,%5,%6,%7},{%8,%9},{%0,%1,%2,%3};\n"
        : "+f"(d[0]), "+f"(d[1]), "+f"(d[2]), "+f"(d[3])
        : "r"(a0), "r"(a1), "r"(a2), "r"(a3), "r"(b0), "r"(b1));
}

__device__ __forceinline__ uint32_t smem_u32(const void* p) {
    return (uint32_t)__cvta_generic_to_shared(p);
}
__device__ __forceinline__ void cp16(void* dst, const void* src) {
    asm volatile("cp.async.cg.shared.global [%0], [%1], 16;\n"
                 :: "r"(smem_u32(dst)), "l"(src));
}
#define CP_COMMIT() asm volatile("cp.async.commit_group;\n")
#define CP_WAIT(n)  asm volatile("cp.async.wait_group %0;\n" :: "n"(n))

// ---------------------------------------------------------------------------
// tf32 warp tile: MT*16 rows (base rb), 32 cols (base cb). B regs reused over m.
// ---------------------------------------------------------------------------
template<int MT>
__device__ __forceinline__ void warp_mma_t(const float* __restrict__ A_s, int rb,
                                           const float* __restrict__ B_s, int cb,
                                           int g, int c, float acc[MT][4][4])
{
    #pragma unroll
    for (int k = 0; k < 16; k++) {
        const int kc = k * 8 + c;
        uint32_t b0[4], b1[4];
        #pragma unroll
        for (int nt = 0; nt < 4; nt++) {
            const int col = cb + nt * 8 + g;
            b0[nt] = __float_as_uint(B_s[kc * GPAD + col]);
            b1[nt] = __float_as_uint(B_s[(kc + 4) * GPAD + col]);
        }
        #pragma unroll
        for (int m = 0; m < MT; m++) {
            const int r0 = (rb + m * 16 + g) * GPAD + kc;
            const int r1 = (rb + m * 16 + g + 8) * GPAD + kc;
            uint32_t a0 = __float_as_uint(A_s[r0]);
            uint32_t a1 = __float_as_uint(A_s[r1]);
            uint32_t a2 = __float_as_uint(A_s[r0 + 4]);
            uint32_t a3 = __float_as_uint(A_s[r1 + 4]);
            #pragma unroll
            for (int nt = 0; nt < 4; nt++)
                mma_tf32(acc[m][nt], a0, a1, a2, a3, b0[nt], b1[nt]);
        }
    }
}

// ---------------------------------------------------------------------------
// in2f: y = ssp( ssp(x) @ W + b ).  64 rows/CTA, 256 threads, grid 128.
// ---------------------------------------------------------------------------
__global__ void __launch_bounds__(256)
in2f_kernel(const float* __restrict__ x, const float* __restrict__ W,
            const float* __restrict__ bias, float* __restrict__ y)
{
    extern __shared__ float sm[];
    float* A_s = sm;             // 64 x GPAD
    float* W_s = sm + 64 * GPAD; // 128 x GPAD
    const int tid = threadIdx.x, w = tid >> 5, lane = tid & 31;
    const int g = lane >> 2, c = lane & 3;
    const int h = w >> 2, q = w & 3;
    const int row0 = blockIdx.x * 64;

    for (int i = tid; i < 4096; i += 256) {
        int r = i >> 5, c4 = (i & 31) << 2;
        cp16(W_s + r * GPAD + c4, W + r * 128 + c4);
    }
    CP_COMMIT();
    for (int i = tid; i < 2048; i += 256) {
        int r = i >> 5, c4 = (i & 31) << 2;
        float4 v = *reinterpret_cast<const float4*>(x + (size_t)(row0 + r) * 128 + c4);
        v.x = to_tf32(sspf(v.x)); v.y = to_tf32(sspf(v.y));
        v.z = to_tf32(sspf(v.z)); v.w = to_tf32(sspf(v.w));
        *reinterpret_cast<float4*>(A_s + r * GPAD + c4) = v;
    }
    CP_WAIT(0);
    __syncthreads();

    float acc[2][4][4];
    #pragma unroll
    for (int m = 0; m < 2; m++)
        #pragma unroll
        for (int nt = 0; nt < 4; nt++)
            acc[m][nt][0] = acc[m][nt][1] = acc[m][nt][2] = acc[m][nt][3] = 0.f;
    warp_mma_t<2>(A_s, h * 32, W_s, q * 32, g, c, acc);

    #pragma unroll
    for (int m = 0; m < 2; m++) {
        const int r0 = row0 + h * 32 + m * 16 + g, r1 = r0 + 8;
        #pragma unroll
        for (int nt = 0; nt < 4; nt++)
            #pragma unroll
            for (int e = 0; e < 2; e++) {
                int f = q * 32 + nt * 8 + c * 2 + e;
                float b = bias[f];
                y[(size_t)r0 * 128 + f] = sspf(acc[m][nt][e] + b);
                y[(size_t)r1 * 128 + f] = sspf(acc[m][nt][2 + e] + b);
            }
    }
}

// ---------------------------------------------------------------------------
// fused MLP.  64 rows/CTA, 256 threads, grid 128.
// ---------------------------------------------------------------------------
__global__ void __launch_bounds__(256)
mlp_kernel(const float* __restrict__ z, const float* __restrict__ resW,
           const float* __restrict__ resB, const float* __restrict__ dW,
           const float* __restrict__ dB, const float* __restrict__ mpar,
           const float* __restrict__ x, float* __restrict__ out)
{
    extern __shared__ float sm[];
    float* A_s = sm;
    float* W_s = sm + 64 * GPAD;
    const int tid = threadIdx.x, w = tid >> 5, lane = tid & 31;
    const int g = lane >> 2, c = lane & 3;
    const int h = w >> 2, q = w & 3;
    const int row0 = blockIdx.x * 64;

    const float* Wp[4] = { resW, resW + 16384, resW + 32768, dW };

    for (int i = tid; i < 4096; i += 256) {
        int r = i >> 5, c4 = (i & 31) << 2;
        cp16(W_s + r * GPAD + c4, Wp[0] + r * 128 + c4);
    }
    CP_COMMIT();
    for (int i = tid; i < 2048; i += 256) {
        int r = i >> 5, c4 = (i & 31) << 2;
        float4 v = *reinterpret_cast<const float4*>(z + (size_t)(row0 + r) * 128 + c4);
        v.x = to_tf32(sspf(v.x)); v.y = to_tf32(sspf(v.y));
        v.z = to_tf32(sspf(v.z)); v.w = to_tf32(sspf(v.w));
        *reinterpret_cast<float4*>(A_s + r * GPAD + c4) = v;
    }
    CP_WAIT(0);
    __syncthreads();

    float acc[2][4][4];
    #pragma unroll
    for (int m = 0; m < 2; m++)
        #pragma unroll
        for (int nt = 0; nt < 4; nt++)
            acc[m][nt][0] = acc[m][nt][1] = acc[m][nt][2] = acc[m][nt][3] = 0.f;
    warp_mma_t<2>(A_s, h * 32, W_s, q * 32, g, c, acc);

    #pragma unroll
    for (int s = 1; s < 4; s++) {
        __syncthreads();                       // readers done with A_s / W_s
        for (int i = tid; i < 4096; i += 256) {
            int r = i >> 5, c4 = (i & 31) << 2;
            cp16(W_s + r * GPAD + c4, Wp[s] + r * 128 + c4);
        }
        CP_COMMIT();
        const float* bs = resB + (s - 1) * 128;
        #pragma unroll
        for (int m = 0; m < 2; m++) {
            const int gr0 = row0 + h * 32 + m * 16 + g, gr1 = gr0 + 8;
            const int sr0 = (h * 32 + m * 16 + g) * GPAD, sr1 = sr0 + 8 * GPAD;
            #pragma unroll
            for (int nt = 0; nt < 4; nt++)
                #pragma unroll
                for (int e = 0; e < 2; e++) {
                    int f = q * 32 + nt * 8 + c * 2 + e;
                    float b = bs[f];
                    float v0 = acc[m][nt][e] + b;
                    float v1 = acc[m][nt][2 + e] + b;
                    if (s == 3) {
                        v0 += z[(size_t)gr0 * 128 + f];
                        v1 += z[(size_t)gr1 * 128 + f];
                    }
                    A_s[sr0 + f] = to_tf32(sspf(v0));
                    A_s[sr1 + f] = to_tf32(sspf(v1));
                }
        }
        #pragma unroll
        for (int m = 0; m < 2; m++)
            #pragma unroll
            for (int nt = 0; nt < 4; nt++)
                acc[m][nt][0] = acc[m][nt][1] = acc[m][nt][2] = acc[m][nt][3] = 0.f;
        CP_WAIT(0);
        __syncthreads();
        warp_mma_t<2>(A_s, h * 32, W_s, q * 32, g, c, acc);
    }

    #pragma unroll
    for (int m = 0; m < 2; m++) {
        const int r0 = row0 + h * 32 + m * 16 + g, r1 = r0 + 8;
        #pragma unroll
        for (int nt = 0; nt < 4; nt++)
            #pragma unroll
            for (int e = 0; e < 2; e++) {
                int f = q * 32 + nt * 8 + c * 2 + e;
                float b = dB[f], mp = mpar[f];
                out[(size_t)r0 * 128 + f] = acc[m][nt][e]     + b + mp * x[(size_t)r0 * 128 + f];
                out[(size_t)r1 * 128 + f] = acc[m][nt][2 + e] + b + mp * x[(size_t)r1 * 128 + f];
            }
    }
}

// ---------------------------------------------------------------------------
// cfconv (fp16 MMA).  16 atoms/CTA, grid 512, 128 threads, 2 CTA/SM.
//   A = half(f_ij * mask)  [64 x 64pad], B = half(G^T) [128 x 64pad]
//   Wf = A @ B^T (m16n8k16), y2[f] = sum_n Wf[n,f]*y[nbr[n],f], z = y + y2
// Pipeline: nb/mk preloaded for all 16 atoms; gather(i+1) issued at iter i
// (consumed at epilogue i+1); f_ij staged LDG->regs->STS under MMA cover.
// One __syncthreads per iteration.
// ---------------------------------------------------------------------------
__global__ void __launch_bounds__(128)
conv_kernel(const float* __restrict__ y, const int* __restrict__ nbrs,
            const float* __restrict__ mask, const float* __restrict__ fij,
            const float* __restrict__ GW, float* __restrict__ out)
{
    extern __shared__ char smc[];
    float*  Ym   = (float*)smc;                               // 2 x 64 x GPAD
    int*    nb_s = (int*)(smc + 2 * 64 * GPAD * 4);           // 16 x 64
    float*  mk_s = (float*)((char*)nb_s + 16 * 64 * 4);       // 16 x 64
    __half* G_t  = (__half*)((char*)mk_s + 16 * 64 * 4);      // 128 x KHP
    __half* A_h  = (__half*)((char*)G_t + 128 * KHP * 2);     // 2 x 64 x KHP

    const int tid = threadIdx.x, w = tid >> 5, lane = tid & 31;
    const int g = lane >> 2, c = lane & 3;
    const int p0 = blockIdx.x * 16;
    const float* yb = y + ((size_t)(p0 >> 10) << 10) * 128;   // batch base

    // zero G_t + A_h (covers K pad cols 50..63; stores below only touch 0..49)
    {
        uint32_t* zp = (uint32_t*)G_t;                        // G_t+A_h contiguous
        for (int i = tid; i < (128 + 2 * 64) * (KHP / 2); i += 128) zp[i] = 0;
    }
    __syncthreads();
    // G transposed to [f][s] half
    for (int i = tid; i < 50 * 128; i += 128) {
        int s = i >> 7, f = i & 127;
        G_t[f * KHP + s] = __float2half_rn(GW[i]);
    }
    // preload nb / mk for all 16 atoms
    for (int i = tid; i < 256; i += 128) cp16(nb_s + i * 4, nbrs + (size_t)p0 * 64 + i * 4);
    for (int i = tid; i < 256; i += 128) cp16(mk_s + i * 4, mask + (size_t)p0 * 64 + i * 4);
    CP_COMMIT();
    CP_WAIT(0);
    __syncthreads();

    // atom 0 f_ij -> A_h[0] (masked)
    {
        const float* fp = fij + (size_t)p0 * 3200;
        for (int i = tid; i < 1600; i += 128) {
            int n = i / 25, s2 = i - n * 25;
            float2 v = *(const float2*)(fp + i * 2);
            float mkv = mk_s[n];
            *(__half2*)(A_h + n * KHP + s2 * 2) = __floats2half2_rn(v.x * mkv, v.y * mkv);
        }
    }
    // gather(0)
    #pragma unroll
    for (int j = 0; j < 16; j++) {
        int idx = tid + j * 128;
        int row = idx >> 5, col = (idx & 31) << 2;
        cp16(Ym + row * GPAD + col, yb + (size_t)nb_s[row] * 128 + col);
    }
    CP_COMMIT();

    for (int it = 0; it < 16; it++) {
        const int cur = it & 1, nxt = cur ^ 1;
        const int p = p0 + it;

        CP_WAIT(0);         // gather(it) complete
        __syncthreads();    // Ym[cur] + A_h[cur] visible; Ym[nxt]/A_h[nxt] free

        // stage f_ij(it+1) into registers (LDG latency hidden by MMA below)
        float2 rf[13];
        if (it < 15) {
            const float* fp = fij + (size_t)(p + 1) * 3200;
            #pragma unroll
            for (int j = 0; j < 13; j++) {
                int i2 = tid + j * 128;
                if (i2 < 1600) rf[j] = *(const float2*)(fp + i2 * 2);
            }
            // gather(it+1)
            const int* nbn = nb_s + (it + 1) * 64;
            float* Yn = Ym + nxt * 64 * GPAD;
            #pragma unroll
            for (int j = 0; j < 16; j++) {
                int idx = tid + j * 128;
                int row = idx >> 5, col = (idx & 31) << 2;
                cp16(Yn + row * GPAD + col, yb + (size_t)nbn[row] * 128 + col);
            }
        }
        CP_COMMIT();

        // MMA: Wf = A_h[cur] @ G_t^T   (m64 rows, warp cols w*32..w*32+31)
        float acc[4][4][4];
        #pragma unroll
        for (int m = 0; m < 4; m++)
            #pragma unroll
            for (int nt = 0; nt < 4; nt++)
                acc[m][nt][0] = acc[m][nt][1] = acc[m][nt][2] = acc[m][nt][3] = 0.f;
        {
            const __half* Ah = A_h + cur * 64 * KHP;
            #pragma unroll
            for (int k = 0; k < 4; k++) {
                const int kc = k * 16 + c * 2;
                uint32_t b0[4], b1[4];
                #pragma unroll
                for (int nt = 0; nt < 4; nt++) {
                    const int col = w * 32 + nt * 8 + g;
                    b0[nt] = *(const uint32_t*)(G_t + col * KHP + kc);
                    b1[nt] = *(const uint32_t*)(G_t + col * KHP + kc + 8);
                }
                #pragma unroll
                for (int m = 0; m < 4; m++) {
                    const __half* ar0 = Ah + (m * 16 + g) * KHP + kc;
                    const __half* ar1 = Ah + (m * 16 + g + 8) * KHP + kc;
                    uint32_t a0 = *(const uint32_t*)ar0;
                    uint32_t a1 = *(const uint32_t*)ar1;
                    uint32_t a2 = *(const uint32_t*)(ar0 + 8);
                    uint32_t a3 = *(const uint32_t*)(ar1 + 8);
                    #pragma unroll
                    for (int nt = 0; nt < 4; nt++)
                        mma_f16(acc[m][nt], a0, a1, a2, a3, b0[nt], b1[nt]);
                }
            }
        }

        // store staged f_ij(it+1) (masked, fp16) -> A_h[nxt]
        if (it < 15) {
            const float* mkn = mk_s + (it + 1) * 64;
            __half* An = A_h + nxt * 64 * KHP;
            #pragma unroll
            for (int j = 0; j < 13; j++) {
                int i2 = tid + j * 128;
                if (i2 < 1600) {
                    int n = i2 / 25, s2 = i2 - n * 25;
                    float mkv = mkn[n];
                    *(__half2*)(An + n * KHP + s2 * 2) =
                        __floats2half2_rn(rf[j].x * mkv, rf[j].y * mkv);
                }
            }
        }

        // epilogue: y2[f] = sum_n Wf[n,f]*Ym[n,f] (mask already folded into Wf)
        const float* Yc = Ym + cur * 64 * GPAD;
        #pragma unroll
        for (int nt = 0; nt < 4; nt++)
            #pragma unroll
            for (int e = 0; e < 2; e++) {
                const int f = w * 32 + nt * 8 + c * 2 + e;
                float s = 0.f;
                #pragma unroll
                for (int m = 0; m < 4; m++) {
                    s += acc[m][nt][e]     * Yc[(m * 16 + g)     * GPAD + f];
                    s += acc[m][nt][2 + e] * Yc[(m * 16 + g + 8) * GPAD + f];
                }
                s += __shfl_xor_sync(0xffffffffu, s, 16);
                s += __shfl_xor_sync(0xffffffffu, s, 8);
                s += __shfl_xor_sync(0xffffffffu, s, 4);
                if (g == 0)
                    out[(size_t)p * 128 + f] = y[(size_t)p * 128 + f] + s;
            }
    }
}

// ---------------------------------------------------------------------------
extern "C" void kernel_launch(void* const* d_in, const int* in_sizes, int n_in,
                              void* d_out, int out_size)
{
    const float* x       = (const float*)d_in[0];
    const int*   nbrs    = (const int*)  d_in[2];
    const float* nmask   = (const float*)d_in[3];
    const float* fij     = (const float*)d_in[4];
    const float* in2f_W  = (const float*)d_in[5];
    const float* in2f_b  = (const float*)d_in[6];
    const float* G_W     = (const float*)d_in[7];
    const float* res_Ws  = (const float*)d_in[8];
    const float* res_bs  = (const float*)d_in[9];
    const float* dense_W = (const float*)d_in[10];
    const float* dense_b = (const float*)d_in[11];
    const float* mask_p  = (const float*)d_in[12];
    float* out = (float*)d_out;

    float *y, *z;
    cudaGetSymbolAddress((void**)&y, g_y);
    cudaGetSymbolAddress((void**)&z, g_z);

    const int smem_d    = (64 * GPAD + 128 * GPAD) * sizeof(float);     // ~99 KB
    const int smem_conv = 2 * 64 * GPAD * 4 + 16 * 64 * 4 * 2
                        + 128 * KHP * 2 + 2 * 64 * KHP * 2;             // ~110 KB

    cudaFuncSetAttribute(in2f_kernel, cudaFuncAttributeMaxDynamicSharedMemorySize, smem_d);
    cudaFuncSetAttribute(mlp_kernel,  cudaFuncAttributeMaxDynamicSharedMemorySize, smem_d);
    cudaFuncSetAttribute(conv_kernel, cudaFuncAttributeMaxDynamicSharedMemorySize, smem_conv);

    in2f_kernel<<<BA / 64, 256, smem_d>>>(x, in2f_W, in2f_b, y);
    conv_kernel<<<BA / 16, 128, smem_conv>>>(y, nbrs, nmask, fij, G_W, z);
    mlp_kernel<<<BA / 64, 256, smem_d>>>(z, res_Ws, res_bs, dense_W, dense_b,
                                         mask_p, x, out);
}

// round 5
// speedup vs baseline: 3.4341x; 1.1505x over previous
#include <cuda_runtime.h>
#include <cuda_fp16.h>
#include <cstdint>

// ---------------------------------------------------------------------------
// InteractionBlock — B=8, A=1024, N=64, F=128, S=50
// prep (G->fp16) | in2f (tf32, k-split W dbuf) | cfconv (fp16 MMA, fp16 gather,
// 3-deep gather pipeline) | fused MLP (tf32, k-split W dbuf)
// ---------------------------------------------------------------------------

#define BA   8192
#define LN2F 0.6931471805599453f
#define GPAD 132     // fp32 smem row stride
#define KHP  72      // conv A/G row stride (halves)
#define YMS  136     // conv Ym row stride (halves)

__device__ float  g_y [BA * 128];
__device__ __half g_yh[BA * 128];
__device__ float  g_z [BA * 128];
__device__ __half g_Gt[128 * KHP];

__device__ __forceinline__ float sspf(float x) {
    return fmaxf(x, 0.f) + __logf(1.f + __expf(-fabsf(x))) - LN2F;
}
__device__ __forceinline__ float to_tf32(float x) {
    uint32_t u; asm("cvt.rna.tf32.f32 %0, %1;" : "=r"(u) : "f"(x));
    return __uint_as_float(u);
}
__device__ __forceinline__ void mma_tf32(float* d,
        uint32_t a0, uint32_t a1, uint32_t a2, uint32_t a3,
        uint32_t b0, uint32_t b1) {
    asm volatile(
        "mma.sync.aligned.m16n8k8.row.col.f32.tf32.tf32.f32 "
        "{%0,%1,%2,%3},{%4,%5,%6,%7},{%8,%9},{%0,%1,%2,%3};\n"
        : "+f"(d[0]), "+f"(d[1]), "+f"(d[2]), "+f"(d[3])
        : "r"(a0), "r"(a1), "r"(a2), "r"(a3), "r"(b0), "r"(b1));
}
__device__ __forceinline__ void mma_f16(float* d,
        uint32_t a0, uint32_t a1, uint32_t a2, uint32_t a3,
        uint32_t b0, uint32_t b1) {
    asm volatile(
        "mma.sync.aligned.m16n8k16.row.col.f32.f16.f16.f32 "
        "{%0,%1,%2,%3},{%4,%5,%6,%7},{%8,%9},{%0,%1,%2,%3};\n"
        : "+f"(d[0]), "+f"(d[1]), "+f"(d[2]), "+f"(d[3])
        : "r"(a0), "r"(a1), "r"(a2), "r"(a3), "r"(b0), "r"(b1));
}
__device__ __forceinline__ uint32_t smem_u32(const void* p) {
    return (uint32_t)__cvta_generic_to_shared(p);
}
__device__ __forceinline__ void cp16(void* dst, const void* src) {
    asm volatile("cp.async.cg.shared.global [%0], [%1], 16;\n"
                 :: "r"(smem_u32(dst)), "l"(src));
}
#define CP_COMMIT() asm volatile("cp.async.commit_group;\n")
#define CP_WAIT(n)  asm volatile("cp.async.wait_group %0;\n" :: "n"(n))

// ---------------------------------------------------------------------------
// prep: G [50,128] -> g_Gt [f][s] fp16, zero-padded to KHP.
// ---------------------------------------------------------------------------
__global__ void prep_kernel(const float* __restrict__ GW)
{
    int i = blockIdx.x * 256 + threadIdx.x;
    if (i < 128 * KHP) {
        int f = i / KHP, s = i - f * KHP;
        g_Gt[i] = (s < 50) ? __float2half_rn(GW[s * 128 + f]) : __float2half_rn(0.f);
    }
}

// ---------------------------------------------------------------------------
// tf32 warp tile: 2x16 rows, 32 cols (base cb), 8 k-steps at A-col offset koff.
// ---------------------------------------------------------------------------
__device__ __forceinline__ void warp_mma8(const float* __restrict__ A_s, int koff,
                                          const float* __restrict__ B_s, int cb,
                                          int g, int c, float acc[2][4][4])
{
    #pragma unroll
    for (int k = 0; k < 8; k++) {
        const int kc = k * 8 + c;
        uint32_t b0[4], b1[4];
        #pragma unroll
        for (int nt = 0; nt < 4; nt++) {
            const int col = cb + nt * 8 + g;
            b0[nt] = __float_as_uint(B_s[kc * GPAD + col]);
            b1[nt] = __float_as_uint(B_s[(kc + 4) * GPAD + col]);
        }
        #pragma unroll
        for (int m = 0; m < 2; m++) {
            const int r0 = (m * 16 + g) * GPAD + koff + kc;
            const int r1 = (m * 16 + g + 8) * GPAD + koff + kc;
            uint32_t a0 = __float_as_uint(A_s[r0]);
            uint32_t a1 = __float_as_uint(A_s[r1]);
            uint32_t a2 = __float_as_uint(A_s[r0 + 4]);
            uint32_t a3 = __float_as_uint(A_s[r1 + 4]);
            #pragma unroll
            for (int nt = 0; nt < 4; nt++)
                mma_tf32(acc[m][nt], a0, a1, a2, a3, b0[nt], b1[nt]);
        }
    }
}

// ---------------------------------------------------------------------------
// in2f: y = ssp( ssp(x) @ W + b ), writes fp32 y and fp16 y_h.
// 32 rows/CTA, 128 threads, grid 256. W loaded in two 64-row halves (dbuf).
// ---------------------------------------------------------------------------
__global__ void __launch_bounds__(128)
in2f_kernel(const float* __restrict__ x, const float* __restrict__ W,
            const float* __restrict__ bias,
            float* __restrict__ y, __half* __restrict__ yh)
{
    extern __shared__ float sm[];
    float* A_s = sm;                  // 32 x GPAD
    float* W0  = sm + 32 * GPAD;      // 64 x GPAD
    float* W1  = W0 + 64 * GPAD;      // 64 x GPAD
    const int tid = threadIdx.x, w = tid >> 5, lane = tid & 31;
    const int g = lane >> 2, c = lane & 3;
    const int row0 = blockIdx.x * 32;

    for (int i = tid; i < 2048; i += 128) {
        int r = i >> 5, c4 = (i & 31) << 2;
        cp16(W0 + r * GPAD + c4, W + r * 128 + c4);
    }
    CP_COMMIT();
    for (int i = tid; i < 2048; i += 128) {
        int r = i >> 5, c4 = (i & 31) << 2;
        cp16(W1 + r * GPAD + c4, W + (64 + r) * 128 + c4);
    }
    CP_COMMIT();
    for (int i = tid; i < 1024; i += 128) {
        int r = i >> 5, c4 = (i & 31) << 2;
        float4 v = *reinterpret_cast<const float4*>(x + (size_t)(row0 + r) * 128 + c4);
        v.x = to_tf32(sspf(v.x)); v.y = to_tf32(sspf(v.y));
        v.z = to_tf32(sspf(v.z)); v.w = to_tf32(sspf(v.w));
        *reinterpret_cast<float4*>(A_s + r * GPAD + c4) = v;
    }

    float acc[2][4][4];
    #pragma unroll
    for (int m = 0; m < 2; m++)
        #pragma unroll
        for (int nt = 0; nt < 4; nt++)
            acc[m][nt][0] = acc[m][nt][1] = acc[m][nt][2] = acc[m][nt][3] = 0.f;

    CP_WAIT(1);
    __syncthreads();
    warp_mma8(A_s, 0, W0, w * 32, g, c, acc);
    CP_WAIT(0);
    __syncthreads();
    warp_mma8(A_s, 64, W1, w * 32, g, c, acc);

    #pragma unroll
    for (int m = 0; m < 2; m++) {
        const int r0 = row0 + m * 16 + g, r1 = r0 + 8;
        #pragma unroll
        for (int nt = 0; nt < 4; nt++) {
            const int f = w * 32 + nt * 8 + c * 2;
            float b0 = bias[f], b1 = bias[f + 1];
            float v00 = sspf(acc[m][nt][0] + b0);
            float v01 = sspf(acc[m][nt][1] + b1);
            float v10 = sspf(acc[m][nt][2] + b0);
            float v11 = sspf(acc[m][nt][3] + b1);
            y[(size_t)r0 * 128 + f]     = v00;
            y[(size_t)r0 * 128 + f + 1] = v01;
            y[(size_t)r1 * 128 + f]     = v10;
            y[(size_t)r1 * 128 + f + 1] = v11;
            *(__half2*)(yh + (size_t)r0 * 128 + f) = __floats2half2_rn(v00, v01);
            *(__half2*)(yh + (size_t)r1 * 128 + f) = __floats2half2_rn(v10, v11);
        }
    }
}

// ---------------------------------------------------------------------------
// fused MLP: 3 residual layers + final dense, k-split double-buffered W.
// 32 rows/CTA, 128 threads, grid 256.
// ---------------------------------------------------------------------------
__global__ void __launch_bounds__(128)
mlp_kernel(const float* __restrict__ z, const float* __restrict__ resW,
           const float* __restrict__ resB, const float* __restrict__ dW,
           const float* __restrict__ dB, const float* __restrict__ mpar,
           const float* __restrict__ x, float* __restrict__ out)
{
    extern __shared__ float sm[];
    float* A_s = sm;                  // 32 x GPAD
    float* W0  = sm + 32 * GPAD;      // 64 x GPAD
    float* W1  = W0 + 64 * GPAD;      // 64 x GPAD
    const int tid = threadIdx.x, w = tid >> 5, lane = tid & 31;
    const int g = lane >> 2, c = lane & 3;
    const int row0 = blockIdx.x * 32;

    const float* Wp[4] = { resW, resW + 16384, resW + 32768, dW };

    // prologue: W halves of layer 0, build A = tf32(ssp(z))
    for (int i = tid; i < 2048; i += 128) {
        int r = i >> 5, c4 = (i & 31) << 2;
        cp16(W0 + r * GPAD + c4, Wp[0] + r * 128 + c4);
    }
    CP_COMMIT();
    for (int i = tid; i < 2048; i += 128) {
        int r = i >> 5, c4 = (i & 31) << 2;
        cp16(W1 + r * GPAD + c4, Wp[0] + (64 + r) * 128 + c4);
    }
    CP_COMMIT();
    for (int i = tid; i < 1024; i += 128) {
        int r = i >> 5, c4 = (i & 31) << 2;
        float4 v = *reinterpret_cast<const float4*>(z + (size_t)(row0 + r) * 128 + c4);
        v.x = to_tf32(sspf(v.x)); v.y = to_tf32(sspf(v.y));
        v.z = to_tf32(sspf(v.z)); v.w = to_tf32(sspf(v.w));
        *reinterpret_cast<float4*>(A_s + r * GPAD + c4) = v;
    }
    CP_WAIT(1);         // W0 ready (W1 may be in flight)
    __syncthreads();

    #pragma unroll
    for (int s = 0; s < 4; s++) {
        float acc[2][4][4];
        #pragma unroll
        for (int m = 0; m < 2; m++)
            #pragma unroll
            for (int nt = 0; nt < 4; nt++)
                acc[m][nt][0] = acc[m][nt][1] = acc[m][nt][2] = acc[m][nt][3] = 0.f;

        warp_mma8(A_s, 0, W0, w * 32, g, c, acc);
        __syncthreads();                        // all warps done with W0
        if (s < 3) {                            // prefetch next layer's half0
            for (int i = tid; i < 2048; i += 128) {
                int r = i >> 5, c4 = (i & 31) << 2;
                cp16(W0 + r * GPAD + c4, Wp[s + 1] + r * 128 + c4);
            }
        }
        CP_COMMIT();
        CP_WAIT(1);                             // W1(s) ready
        __syncthreads();
        warp_mma8(A_s, 64, W1, w * 32, g, c, acc);
        __syncthreads();                        // done with W1 and A_s
        if (s < 3) {                            // prefetch next layer's half1
            for (int i = tid; i < 2048; i += 128) {
                int r = i >> 5, c4 = (i & 31) << 2;
                cp16(W1 + r * GPAD + c4, Wp[s + 1] + (64 + r) * 128 + c4);
            }
        }
        CP_COMMIT();

        if (s < 3) {
            const float* bs = resB + s * 128;
            #pragma unroll
            for (int m = 0; m < 2; m++) {
                const int gr0 = row0 + m * 16 + g, gr1 = gr0 + 8;
                const int sr0 = (m * 16 + g) * GPAD, sr1 = sr0 + 8 * GPAD;
                #pragma unroll
                for (int nt = 0; nt < 4; nt++)
                    #pragma unroll
                    for (int e = 0; e < 2; e++) {
                        int f = w * 32 + nt * 8 + c * 2 + e;
                        float b = bs[f];
                        float v0 = acc[m][nt][e] + b;
                        float v1 = acc[m][nt][2 + e] + b;
                        if (s == 2) {           // y = z + h3, A = ssp(y)
                            v0 += z[(size_t)gr0 * 128 + f];
                            v1 += z[(size_t)gr1 * 128 + f];
                        }
                        A_s[sr0 + f] = to_tf32(sspf(v0));
                        A_s[sr1 + f] = to_tf32(sspf(v1));
                    }
            }
            CP_WAIT(1);                         // next W0 ready
            __syncthreads();                    // A rewrite visible
        } else {
            #pragma unroll
            for (int m = 0; m < 2; m++) {
                const int r0 = row0 + m * 16 + g, r1 = r0 + 8;
                #pragma unroll
                for (int nt = 0; nt < 4; nt++)
                    #pragma unroll
                    for (int e = 0; e < 2; e++) {
                        int f = w * 32 + nt * 8 + c * 2 + e;
                        float b = dB[f], mp = mpar[f];
                        out[(size_t)r0 * 128 + f] =
                            acc[m][nt][e]     + b + mp * x[(size_t)r0 * 128 + f];
                        out[(size_t)r1 * 128 + f] =
                            acc[m][nt][2 + e] + b + mp * x[(size_t)r1 * 128 + f];
                    }
            }
        }
    }
}

// ---------------------------------------------------------------------------
// cfconv: 16 atoms/CTA, grid 512, 128 threads, 2 CTA/SM.
// fp16 MMA (mask folded into A), fp16 gather from y_h, gather 2 iters ahead.
// ---------------------------------------------------------------------------
__global__ void __launch_bounds__(128)
conv_kernel(const float* __restrict__ y, const __half* __restrict__ yh,
            const int* __restrict__ nbrs, const float* __restrict__ mask,
            const float* __restrict__ fij, float* __restrict__ out)
{
    extern __shared__ char smc[];
    __half* Ym   = (__half*)smc;                                // 3 x 64 x YMS
    __half* G_t  = Ym + 3 * 64 * YMS;                           // 128 x KHP
    __half* A_h  = G_t + 128 * KHP;                             // 2 x 64 x KHP
    int*    nb_s = (int*)(A_h + 2 * 64 * KHP);                  // 16 x 64
    float*  mk_s = (float*)(nb_s + 16 * 64);                    // 16 x 64

    const int tid = threadIdx.x, w = tid >> 5, lane = tid & 31;
    const int g = lane >> 2, c = lane & 3;
    const int p0 = blockIdx.x * 16;
    const __half* yhb = yh + ((size_t)(p0 >> 10) << 10) * 128;  // batch base

    // zero A_h (pad cols must stay 0)
    for (int i = tid; i < 2 * 64 * (KHP / 2); i += 128) ((uint32_t*)A_h)[i] = 0;

    // prologue loads: G_t, nb, mk
    for (int i = tid; i < 1152; i += 128)
        cp16(G_t + i * 8, g_Gt + i * 8);
    for (int i = tid; i < 256; i += 128) cp16(nb_s + i * 4, nbrs + (size_t)p0 * 64 + i * 4);
    for (int i = tid; i < 256; i += 128) cp16(mk_s + i * 4, mask + (size_t)p0 * 64 + i * 4);
    CP_COMMIT();
    CP_WAIT(0);
    __syncthreads();

    // gather(0), gather(1): 64 rows x 16 cp16 (fp16 rows, 256B) = 8/thread
    #pragma unroll
    for (int j = 0; j < 8; j++) {
        int idx = tid + j * 128;
        int row = idx >> 4, col = (idx & 15) << 3;   // col in halves
        cp16(Ym + row * YMS + col, yhb + (size_t)nb_s[row] * 128 + col);
    }
    CP_COMMIT();
    #pragma unroll
    for (int j = 0; j < 8; j++) {
        int idx = tid + j * 128;
        int row = idx >> 4, col = (idx & 15) << 3;
        cp16(Ym + 64 * YMS + row * YMS + col,
             yhb + (size_t)nb_s[64 + row] * 128 + col);
    }
    CP_COMMIT();

    // A_h[0] = half(f_ij(0) * mask(0))
    {
        const float* fp = fij + (size_t)p0 * 3200;
        for (int i = tid; i < 1600; i += 128) {
            int n = i / 25, s2 = i - n * 25;
            float2 v = *(const float2*)(fp + i * 2);
            float mkv = mk_s[n];
            *(__half2*)(A_h + n * KHP + s2 * 2) = __floats2half2_rn(v.x * mkv, v.y * mkv);
        }
    }

    for (int it = 0; it < 16; it++) {
        const int cur = it & 1, nxt = cur ^ 1;
        const int p = p0 + it;

        CP_WAIT(1);          // gather(it) done (gather(it+1) may be in flight)
        __syncthreads();     // Ym[it%3], A_h[cur] visible; Ym[(it+2)%3], A_h[nxt] free

        // issue gather(it+2)
        if (it + 2 < 16) {
            const int* nbn = nb_s + (it + 2) * 64;
            __half* Yn = Ym + ((it + 2) % 3) * 64 * YMS;
            #pragma unroll
            for (int j = 0; j < 8; j++) {
                int idx = tid + j * 128;
                int row = idx >> 4, col = (idx & 15) << 3;
                cp16(Yn + row * YMS + col, yhb + (size_t)nbn[row] * 128 + col);
            }
        }
        CP_COMMIT();

        // stage f_ij(it+1) into registers
        float2 rf[13];
        if (it < 15) {
            const float* fp = fij + (size_t)(p + 1) * 3200;
            #pragma unroll
            for (int j = 0; j < 13; j++) {
                int i2 = tid + j * 128;
                if (i2 < 1600) rf[j] = *(const float2*)(fp + i2 * 2);
            }
        }

        // MMA: Wf = A_h[cur] @ G_t^T  (m64, warp cols w*32..+31)
        float acc[4][4][4];
        #pragma unroll
        for (int m = 0; m < 4; m++)
            #pragma unroll
            for (int nt = 0; nt < 4; nt++)
                acc[m][nt][0] = acc[m][nt][1] = acc[m][nt][2] = acc[m][nt][3] = 0.f;
        {
            const __half* Ah = A_h + cur * 64 * KHP;
            #pragma unroll
            for (int k = 0; k < 4; k++) {
                const int kc = k * 16 + c * 2;
                uint32_t b0[4], b1[4];
                #pragma unroll
                for (int nt = 0; nt < 4; nt++) {
                    const int col = w * 32 + nt * 8 + g;
                    b0[nt] = *(const uint32_t*)(G_t + col * KHP + kc);
                    b1[nt] = *(const uint32_t*)(G_t + col * KHP + kc + 8);
                }
                #pragma unroll
                for (int m = 0; m < 4; m++) {
                    const __half* ar0 = Ah + (m * 16 + g) * KHP + kc;
                    const __half* ar1 = Ah + (m * 16 + g + 8) * KHP + kc;
                    uint32_t a0 = *(const uint32_t*)ar0;
                    uint32_t a1 = *(const uint32_t*)ar1;
                    uint32_t a2 = *(const uint32_t*)(ar0 + 8);
                    uint32_t a3 = *(const uint32_t*)(ar1 + 8);
                    #pragma unroll
                    for (int nt = 0; nt < 4; nt++)
                        mma_f16(acc[m][nt], a0, a1, a2, a3, b0[nt], b1[nt]);
                }
            }
        }

        // store staged f_ij(it+1) masked -> A_h[nxt]
        if (it < 15) {
            const float* mkn = mk_s + (it + 1) * 64;
            __half* An = A_h + nxt * 64 * KHP;
            #pragma unroll
            for (int j = 0; j < 13; j++) {
                int i2 = tid + j * 128;
                if (i2 < 1600) {
                    int n = i2 / 25, s2 = i2 - n * 25;
                    float mkv = mkn[n];
                    *(__half2*)(An + n * KHP + s2 * 2) =
                        __floats2half2_rn(rf[j].x * mkv, rf[j].y * mkv);
                }
            }
        }

        // epilogue: y2[f] = sum_n Wf[n,f] * yh[nbr[n],f]
        const __half* Yc = Ym + (it % 3) * 64 * YMS;
        #pragma unroll
        for (int nt = 0; nt < 4; nt++) {
            const int f0 = w * 32 + nt * 8 + c * 2;   // even f of the pair
            float s0 = 0.f, s1 = 0.f;
            #pragma unroll
            for (int m = 0; m < 4; m++) {
                float2 v0 = __half22float2(*(const __half2*)(Yc + (m * 16 + g)     * YMS + f0));
                float2 v1 = __half22float2(*(const __half2*)(Yc + (m * 16 + g + 8) * YMS + f0));
                s0 += acc[m][nt][0] * v0.x + acc[m][nt][2] * v1.x;
                s1 += acc[m][nt][1] * v0.y + acc[m][nt][3] * v1.y;
            }
            s0 += __shfl_xor_sync(0xffffffffu, s0, 16);
            s0 += __shfl_xor_sync(0xffffffffu, s0, 8);
            s0 += __shfl_xor_sync(0xffffffffu, s0, 4);
            s1 += __shfl_xor_sync(0xffffffffu, s1, 16);
            s1 += __shfl_xor_sync(0xffffffffu, s1, 8);
            s1 += __shfl_xor_sync(0xffffffffu, s1, 4);
            if (g == 0) {
                out[(size_t)p * 128 + f0]     = y[(size_t)p * 128 + f0]     + s0;
                out[(size_t)p * 128 + f0 + 1] = y[(size_t)p * 128 + f0 + 1] + s1;
            }
        }
    }
}

// ---------------------------------------------------------------------------
extern "C" void kernel_launch(void* const* d_in, const int* in_sizes, int n_in,
                              void* d_out, int out_size)
{
    const float* x       = (const float*)d_in[0];
    const int*   nbrs    = (const int*)  d_in[2];
    const float* nmask   = (const float*)d_in[3];
    const float* fij     = (const float*)d_in[4];
    const float* in2f_W  = (const float*)d_in[5];
    const float* in2f_b  = (const float*)d_in[6];
    const float* G_W     = (const float*)d_in[7];
    const float* res_Ws  = (const float*)d_in[8];
    const float* res_bs  = (const float*)d_in[9];
    const float* dense_W = (const float*)d_in[10];
    const float* dense_b = (const float*)d_in[11];
    const float* mask_p  = (const float*)d_in[12];
    float* out = (float*)d_out;

    float  *y, *z;
    __half *yh;
    cudaGetSymbolAddress((void**)&y,  g_y);
    cudaGetSymbolAddress((void**)&z,  g_z);
    cudaGetSymbolAddress((void**)&yh, g_yh);

    const int smem_d    = (32 * GPAD + 2 * 64 * GPAD) * sizeof(float);       // ~84.5 KB
    const int smem_conv = 3 * 64 * YMS * 2 + 128 * KHP * 2
                        + 2 * 64 * KHP * 2 + 16 * 64 * 4 * 2;                // ~97 KB

    cudaFuncSetAttribute(in2f_kernel, cudaFuncAttributeMaxDynamicSharedMemorySize, smem_d);
    cudaFuncSetAttribute(mlp_kernel,  cudaFuncAttributeMaxDynamicSharedMemorySize, smem_d);
    cudaFuncSetAttribute(conv_kernel, cudaFuncAttributeMaxDynamicSharedMemorySize, smem_conv);

    prep_kernel<<<(128 * KHP + 255) / 256, 256>>>(G_W);
    in2f_kernel<<<BA / 32, 128, smem_d>>>(x, in2f_W, in2f_b, y, yh);
    conv_kernel<<<BA / 16, 128, smem_conv>>>(y, yh, nbrs, nmask, fij, z);
    mlp_kernel<<<BA / 32, 128, smem_d>>>(z, res_Ws, res_bs, dense_W, dense_b,
                                         mask_p, x, out);
}